// round 14
// baseline (speedup 1.0000x reference)
#include <cuda_runtime.h>
#include <cuda_fp16.h>
#include <stdint.h>

#define N_NODES 100000
#define D 128
#define MAX_E 1600000
#define BM 128
#define CAP 96            // ELL capacity per node; Poisson(16) => P(deg>96) ~ 0

// ---------------- scratch (static device globals; no runtime alloc) ----------
__device__ __align__(16) int    g_cursor[N_NODES];          // per-node edge count
__device__ __align__(16) int    g_ell[(size_t)N_NODES * CAP];
__device__ __align__(16) __half g_agg16[(size_t)N_NODES * D];
__device__ __align__(16) __half g_x16[(size_t)N_NODES * D];
__device__ __align__(16) __half g_h16[(size_t)N_NODES * D];
__device__ __align__(16) __half g_w16[4 * 128 * 128];   // [W1l|W1r|W2l|W2r] fp16
__device__ int g_not64 = 0;   // sticky dtype flag (set-once, stable across replays)

// ---------------- fused prologue: tohalf | zero_cursor | probe | W->fp16 -----
#define NB_X 12500          // N_NODES*D/4 float4s / 256
#define NB_Z 391
#define NB_P 16
#define NB_W 64             // 4*128*128 floats / 4 / 256

__global__ void k_prep(const float* __restrict__ x, const void* __restrict__ ei,
                       const float* __restrict__ W1l, const float* __restrict__ W1r,
                       const float* __restrict__ W2l, const float* __restrict__ W2r,
                       int E) {
    int b = blockIdx.x;
    int t = threadIdx.x;
    if (b < NB_X) {                              // x -> fp16
        int i = b * 256 + t;
        float4 v = ((const float4*)x)[i];
        __half2 h0 = __floats2half2_rn(v.x, v.y);
        __half2 h1 = __floats2half2_rn(v.z, v.w);
        uint2 u;
        u.x = *(uint32_t*)&h0;
        u.y = *(uint32_t*)&h1;
        ((uint2*)g_x16)[i] = u;
    } else if (b < NB_X + NB_Z) {                // zero per-node cursors
        int i = (b - NB_X) * 256 + t;
        if (i < N_NODES) g_cursor[i] = 0;
    } else if (b < NB_X + NB_Z + NB_P) {         // dtype probe (sticky)
        int i = (b - NB_X - NB_Z) * 256 + t;
        int n = E < 4096 ? E : 4096;
        if (i < n) {
            long long v = ((const long long*)ei)[i];
            if (v < 0 || v >= N_NODES) atomicExch(&g_not64, 1);
        }
    } else {                                     // W -> fp16
        int i = (b - NB_X - NB_Z - NB_P) * 256 + t;   // float4 index 0..16383
        const float* s = (i < 4096) ? W1l : (i < 8192) ? W1r
                        : (i < 12288) ? W2l : W2r;
        float4 v = ((const float4*)s)[i & 4095];
        __half2 h0 = __floats2half2_rn(v.x, v.y);
        __half2 h1 = __floats2half2_rn(v.z, v.w);
        uint2 u;
        u.x = *(uint32_t*)&h0;
        u.y = *(uint32_t*)&h1;
        ((uint2*)g_w16)[i] = u;
    }
}

// ---------------- ELL fill: one pass, no hist/scan ---------------------------
__device__ __forceinline__ int load_idx(const void* ei, long long pos) {
    if (g_not64) return ((const int*)ei)[pos];
    return (int)((const long long*)ei)[pos];
}

__global__ void k_fill(const void* __restrict__ ei, int E) {
    int i = (blockIdx.x * blockDim.x + threadIdx.x) * 2;
#pragma unroll
    for (int q = 0; q < 2; q++) {
        int e = i + q;
        if (e < E) {
            int d = load_idx(ei, (long long)E + e);
            int s = load_idx(ei, e);
            if ((unsigned)d < N_NODES && (unsigned)s < N_NODES) {
                int pos = atomicAdd(&g_cursor[d], 1);
                if (pos < CAP) g_ell[(size_t)d * CAP + pos] = s;
            }
        }
    }
}

// ---------------- aggregation: warp/node, half-warp x 4 edges in flight ------
template <int LAYER>
__global__ void k_agg(void) {
    int gw = (blockIdx.x * blockDim.x + threadIdx.x) >> 5;
    int lane = threadIdx.x & 31;
    if (gw >= N_NODES) return;
    int n = g_cursor[gw];
    int m = n < CAP ? n : CAP;
    const int* col = g_ell + (size_t)gw * CAP;
    int half = lane >> 4;
    int sub = lane & 15;
    const uint4* src = (LAYER == 0) ? (const uint4*)g_x16 : (const uint4*)g_h16;
    float a[8];
#pragma unroll
    for (int q = 0; q < 8; q++) a[q] = 0.f;

    int j = half;
    for (; j + 6 < m; j += 8) {
        int n0 = col[j], n1 = col[j + 2], n2 = col[j + 4], n3 = col[j + 6];
        uint4 u0 = src[(size_t)n0 * 16 + sub];
        uint4 u1 = src[(size_t)n1 * 16 + sub];
        uint4 u2 = src[(size_t)n2 * 16 + sub];
        uint4 u3 = src[(size_t)n3 * 16 + sub];
        float2 f;
        f = __half22float2(*(__half2*)&u0.x); a[0] += f.x; a[1] += f.y;
        f = __half22float2(*(__half2*)&u0.y); a[2] += f.x; a[3] += f.y;
        f = __half22float2(*(__half2*)&u0.z); a[4] += f.x; a[5] += f.y;
        f = __half22float2(*(__half2*)&u0.w); a[6] += f.x; a[7] += f.y;
        f = __half22float2(*(__half2*)&u1.x); a[0] += f.x; a[1] += f.y;
        f = __half22float2(*(__half2*)&u1.y); a[2] += f.x; a[3] += f.y;
        f = __half22float2(*(__half2*)&u1.z); a[4] += f.x; a[5] += f.y;
        f = __half22float2(*(__half2*)&u1.w); a[6] += f.x; a[7] += f.y;
        f = __half22float2(*(__half2*)&u2.x); a[0] += f.x; a[1] += f.y;
        f = __half22float2(*(__half2*)&u2.y); a[2] += f.x; a[3] += f.y;
        f = __half22float2(*(__half2*)&u2.z); a[4] += f.x; a[5] += f.y;
        f = __half22float2(*(__half2*)&u2.w); a[6] += f.x; a[7] += f.y;
        f = __half22float2(*(__half2*)&u3.x); a[0] += f.x; a[1] += f.y;
        f = __half22float2(*(__half2*)&u3.y); a[2] += f.x; a[3] += f.y;
        f = __half22float2(*(__half2*)&u3.z); a[4] += f.x; a[5] += f.y;
        f = __half22float2(*(__half2*)&u3.w); a[6] += f.x; a[7] += f.y;
    }
    for (; j < m; j += 2) {
        int n0 = col[j];
        uint4 u0 = src[(size_t)n0 * 16 + sub];
        float2 f;
        f = __half22float2(*(__half2*)&u0.x); a[0] += f.x; a[1] += f.y;
        f = __half22float2(*(__half2*)&u0.y); a[2] += f.x; a[3] += f.y;
        f = __half22float2(*(__half2*)&u0.z); a[4] += f.x; a[5] += f.y;
        f = __half22float2(*(__half2*)&u0.w); a[6] += f.x; a[7] += f.y;
    }
#pragma unroll
    for (int q = 0; q < 8; q++)
        a[q] += __shfl_down_sync(0xffffffffu, a[q], 16);
    if (half == 0) {
        float inv = 1.0f / fmaxf((float)n, 1.0f);
        __half2 h0 = __floats2half2_rn(a[0] * inv, a[1] * inv);
        __half2 h1 = __floats2half2_rn(a[2] * inv, a[3] * inv);
        __half2 h2 = __floats2half2_rn(a[4] * inv, a[5] * inv);
        __half2 h3 = __floats2half2_rn(a[6] * inv, a[7] * inv);
        uint4 o;
        o.x = *(uint32_t*)&h0;
        o.y = *(uint32_t*)&h1;
        o.z = *(uint32_t*)&h2;
        o.w = *(uint32_t*)&h3;
        ((uint4*)g_agg16)[(size_t)gw * 16 + sub] = o;
    }
}

// ---------------- fp16 mma helper ---------------------------------------------
__device__ __forceinline__ void mma_f16(float d[4], uint32_t a0, uint32_t a1,
                                        uint32_t a2, uint32_t a3,
                                        uint32_t b0, uint32_t b1) {
    asm volatile(
        "mma.sync.aligned.m16n8k16.row.col.f32.f16.f16.f32 "
        "{%0,%1,%2,%3}, {%4,%5,%6,%7}, {%8,%9}, {%0,%1,%2,%3};\n"
        : "+f"(d[0]), "+f"(d[1]), "+f"(d[2]), "+f"(d[3])
        : "r"(a0), "r"(a1), "r"(a2), "r"(a3), "r"(b0), "r"(b1));
}

// ---------------- fused fp16 GEMM: 3-stage cp.async pipeline, XOR swizzle ----
// block 256 thr; tile 128x128; warp tile 32x64; K=256 in 8 chunks of 32.
// __launch_bounds__(256, 3): cap regs at 85 -> 3 blocks/SM (occ 22% -> 37%).
// LAYER 0: A=[agg16|x16], out -> g_h16 (relu). LAYER 1: A=[agg16|h16], out fp32.
template <int LAYER>
__global__ void __launch_bounds__(256, 3)
k_gemm_mma(const float* __restrict__ bb, float* __restrict__ OUT) {
    __shared__ __align__(16) __half As16[3][BM][32];   // 24 KB
    __shared__ __align__(16) __half Ws16[3][32][128];  // 24 KB

    int tid  = threadIdx.x;
    int warp = tid >> 5;
    int lane = tid & 31;
    int rg = warp >> 1;
    int cg = warp & 1;
    int gid = lane >> 2;
    int tig = lane & 3;
    int quad = lane >> 3;
    int lr   = lane & 7;
    int row0 = blockIdx.x * BM;

    const __half* Wbase = g_w16 + LAYER * 32768;

    // cp.async chunk issue: 2x 16B for W + 2x 16B for A per thread (swizzled)
    auto issue_chunk = [&](int ch) {
        const __half* Wsrc = Wbase + (ch < 4 ? 0 : 16384);
        const __half* Asrc = (ch < 4) ? g_agg16 : (LAYER == 0 ? g_x16 : g_h16);
        int kcol = (ch & 3) * 32;
        int buf = ch % 3;
#pragma unroll
        for (int j = 0; j < 2; j++) {
            int u = tid + j * 256;
            int kk = u >> 4, c16 = u & 15;            // W: 16 chunks/row
            int wc = (c16 ^ (kk & 7)) * 8;
            uint32_t wdst = (uint32_t)__cvta_generic_to_shared(&Ws16[buf][kk][wc]);
            const void* wsrc = Wsrc + (size_t)(kcol + kk) * 128 + c16 * 8;
            asm volatile("cp.async.cg.shared.global [%0], [%1], 16;"
                         :: "r"(wdst), "l"(wsrc));
            int r = u >> 2, ac = u & 3;               // A: 4 chunks/row
            int grow = row0 + r;
            int asw = (ac ^ ((r >> 1) & 3)) * 8;
            uint32_t adst = (uint32_t)__cvta_generic_to_shared(&As16[buf][r][asw]);
            const void* asrc = Asrc +
                (size_t)(grow < N_NODES ? grow : 0) * 128 + kcol + ac * 8;
            int sz = (grow < N_NODES) ? 16 : 0;       // OOB rows zero-fill
            asm volatile("cp.async.cg.shared.global [%0], [%1], 16, %2;"
                         :: "r"(adst), "l"(asrc), "r"(sz));
        }
        asm volatile("cp.async.commit_group;");
    };

    float acc[2][8][4];
#pragma unroll
    for (int m = 0; m < 2; m++)
#pragma unroll
        for (int n = 0; n < 8; n++)
#pragma unroll
            for (int j = 0; j < 4; j++) acc[m][n][j] = 0.f;

    issue_chunk(0);
    issue_chunk(1);

    for (int ch = 0; ch < 8; ch++) {
        if (ch < 6) { asm volatile("cp.async.wait_group 1;"); }
        else        { asm volatile("cp.async.wait_group 0;"); }
        __syncthreads();                   // chunk ch resident; mma ch-1 retired
        if (ch < 6) issue_chunk(ch + 2);   // overlaps the next two mma phases
        int buf = ch % 3;

#pragma unroll
        for (int ks = 0; ks < 2; ks++) {
            uint32_t a[2][4];
#pragma unroll
            for (int m = 0; m < 2; m++) {
                int row = rg * 32 + m * 16 + (quad & 1) * 8 + lr;
                int cchunk = ks * 2 + (quad >> 1);
                int col = (cchunk ^ ((row >> 1) & 3)) * 8;
                uint32_t saddr =
                    (uint32_t)__cvta_generic_to_shared(&As16[buf][row][col]);
                asm volatile(
                    "ldmatrix.sync.aligned.m8n8.x4.shared.b16 "
                    "{%0,%1,%2,%3}, [%4];"
                    : "=r"(a[m][0]), "=r"(a[m][1]), "=r"(a[m][2]), "=r"(a[m][3])
                    : "r"(saddr));
            }
#pragma unroll
            for (int np = 0; np < 4; np++) {
                int krow = ks * 16 + (lane & 15);
                int cc = cg * 8 + np * 2 + (lane >> 4);
                int ccol = (cc ^ (krow & 7)) * 8;
                uint32_t saddr =
                    (uint32_t)__cvta_generic_to_shared(&Ws16[buf][krow][ccol]);
                uint32_t b0, b1, b2, b3;
                asm volatile(
                    "ldmatrix.sync.aligned.m8n8.x4.trans.shared.b16 "
                    "{%0,%1,%2,%3}, [%4];"
                    : "=r"(b0), "=r"(b1), "=r"(b2), "=r"(b3) : "r"(saddr));
                mma_f16(acc[0][2 * np],     a[0][0], a[0][1], a[0][2], a[0][3], b0, b1);
                mma_f16(acc[1][2 * np],     a[1][0], a[1][1], a[1][2], a[1][3], b0, b1);
                mma_f16(acc[0][2 * np + 1], a[0][0], a[0][1], a[0][2], a[0][3], b2, b3);
                mma_f16(acc[1][2 * np + 1], a[1][0], a[1][1], a[1][2], a[1][3], b2, b3);
            }
        }
    }
    __syncthreads();

    // RowS scratch aliases the (now dead) As16 buffer
    float* RowS = (float*)&As16[0][0][0];   // [2][BM]

    // ---- epilogue: bias, row sumsq, cross-colgroup reduce, normalize --------
    float bv[8][2];
#pragma unroll
    for (int n = 0; n < 8; n++) {
        bv[n][0] = bb[cg * 64 + n * 8 + tig * 2];
        bv[n][1] = bb[cg * 64 + n * 8 + tig * 2 + 1];
    }

#pragma unroll
    for (int m = 0; m < 2; m++) {
        float s0 = 0.f, s1 = 0.f;
#pragma unroll
        for (int n = 0; n < 8; n++) {
            acc[m][n][0] += bv[n][0];
            acc[m][n][1] += bv[n][1];
            acc[m][n][2] += bv[n][0];
            acc[m][n][3] += bv[n][1];
            s0 = fmaf(acc[m][n][0], acc[m][n][0], s0);
            s0 = fmaf(acc[m][n][1], acc[m][n][1], s0);
            s1 = fmaf(acc[m][n][2], acc[m][n][2], s1);
            s1 = fmaf(acc[m][n][3], acc[m][n][3], s1);
        }
        s0 += __shfl_xor_sync(0xffffffffu, s0, 1);
        s0 += __shfl_xor_sync(0xffffffffu, s0, 2);
        s1 += __shfl_xor_sync(0xffffffffu, s1, 1);
        s1 += __shfl_xor_sync(0xffffffffu, s1, 2);
        if (tig == 0) {
            RowS[cg * BM + rg * 32 + m * 16 + gid]     = s0;
            RowS[cg * BM + rg * 32 + m * 16 + gid + 8] = s1;
        }
    }
    __syncthreads();

#pragma unroll
    for (int m = 0; m < 2; m++) {
        int rl = rg * 32 + m * 16 + gid;
        int rh = rl + 8;
        float inv0 = 1.0f / fmaxf(sqrtf(RowS[rl] + RowS[BM + rl]), 1e-12f);
        float inv1 = 1.0f / fmaxf(sqrtf(RowS[rh] + RowS[BM + rh]), 1e-12f);
        int glo = row0 + rl, ghi = row0 + rh;
#pragma unroll
    for (int p = 0; p < 2; p++) {
            int grow = p ? ghi : glo;
            float inv = p ? inv1 : inv0;
            int o0i = p ? 2 : 0;
            if (grow >= N_NODES) continue;
            if (LAYER == 0) {
                __half* hp = g_h16 + (size_t)grow * 128 + cg * 64 + tig * 2;
#pragma unroll
                for (int n = 0; n < 8; n++) {
                    float o0 = fmaxf(acc[m][n][o0i] * inv, 0.f);
                    float o1 = fmaxf(acc[m][n][o0i + 1] * inv, 0.f);
                    *(__half2*)(hp + n * 8) = __floats2half2_rn(o0, o1);
                }
            } else {
                float* dp = OUT + (size_t)grow * 128 + cg * 64 + tig * 2;
#pragma unroll
                for (int n = 0; n < 8; n++) {
                    float o0 = acc[m][n][o0i] * inv;
                    float o1 = acc[m][n][o0i + 1] * inv;
                    *(float2*)(dp + n * 8) = make_float2(o0, o1);
                }
            }
        }
    }
}

// ---------------- launch ------------------------------------------------------
extern "C" void kernel_launch(void* const* d_in, const int* in_sizes, int n_in,
                              void* d_out, int out_size) {
    const float* x   = (const float*)d_in[0];
    const void*  ei  = d_in[1];
    const float* W1l = (const float*)d_in[2];
    const float* b1  = (const float*)d_in[3];
    const float* W1r = (const float*)d_in[4];
    const float* W2l = (const float*)d_in[5];
    const float* b2  = (const float*)d_in[6];
    const float* W2r = (const float*)d_in[7];

    int E = in_sizes[1] / 2;
    float* out = (float*)d_out;

    int eb2 = (E / 2 + 255) / 256;

    k_prep<<<NB_X + NB_Z + NB_P + NB_W, 256>>>(x, ei, W1l, W1r, W2l, W2r, E);
    k_fill<<<eb2, 256>>>(ei, E);

    int aggBlocks  = (N_NODES * 32 + 255) / 256;
    int gemmBlocks = (N_NODES + BM - 1) / BM;

    // layer 1: agg(x16) -> gemm -> g_h16 (normalize + relu)
    k_agg<0><<<aggBlocks, 256>>>();
    k_gemm_mma<0><<<gemmBlocks, 256>>>(b1, out);

    // layer 2: agg(g_h16) -> gemm -> out (normalize)
    k_agg<1><<<aggBlocks, 256>>>();
    k_gemm_mma<1><<<gemmBlocks, 256>>>(b2, out);
}

// round 15
// speedup vs baseline: 1.0966x; 1.0966x over previous
#include <cuda_runtime.h>
#include <cuda_fp16.h>
#include <stdint.h>

#define N_NODES 100000
#define D 128
#define MAX_E 1600000
#define BM 128
#define NTILES 782          // ceil(N_NODES / BM)
#define GEMM_GRID 296       // 148 SMs x 2 blocks
#define CAP 96            // ELL capacity per node; Poisson(16) => P(deg>96) ~ 0

// ---------------- scratch (static device globals; no runtime alloc) ----------
__device__ __align__(16) int    g_cursor[N_NODES];          // per-node edge count
__device__ __align__(16) int    g_ell[(size_t)N_NODES * CAP];
__device__ __align__(16) __half g_agg16[(size_t)N_NODES * D];
__device__ __align__(16) __half g_x16[(size_t)N_NODES * D];
__device__ __align__(16) __half g_h16[(size_t)N_NODES * D];
__device__ __align__(16) __half g_w16[4 * 128 * 128];   // [W1l|W1r|W2l|W2r] fp16
__device__ int g_not64 = 0;   // sticky dtype flag (set-once, stable across replays)

// ---------------- fused prologue: tohalf | zero_cursor | probe | W->fp16 -----
#define NB_X 12500          // N_NODES*D/4 float4s / 256
#define NB_Z 391
#define NB_P 16
#define NB_W 64             // 4*128*128 floats / 4 / 256

__global__ void k_prep(const float* __restrict__ x, const void* __restrict__ ei,
                       const float* __restrict__ W1l, const float* __restrict__ W1r,
                       const float* __restrict__ W2l, const float* __restrict__ W2r,
                       int E) {
    int b = blockIdx.x;
    int t = threadIdx.x;
    if (b < NB_X) {                              // x -> fp16
        int i = b * 256 + t;
        float4 v = ((const float4*)x)[i];
        __half2 h0 = __floats2half2_rn(v.x, v.y);
        __half2 h1 = __floats2half2_rn(v.z, v.w);
        uint2 u;
        u.x = *(uint32_t*)&h0;
        u.y = *(uint32_t*)&h1;
        ((uint2*)g_x16)[i] = u;
    } else if (b < NB_X + NB_Z) {                // zero per-node cursors
        int i = (b - NB_X) * 256 + t;
        if (i < N_NODES) g_cursor[i] = 0;
    } else if (b < NB_X + NB_Z + NB_P) {         // dtype probe (sticky)
        int i = (b - NB_X - NB_Z) * 256 + t;
        int n = E < 4096 ? E : 4096;
        if (i < n) {
            long long v = ((const long long*)ei)[i];
            if (v < 0 || v >= N_NODES) atomicExch(&g_not64, 1);
        }
    } else {                                     // W -> fp16
        int i = (b - NB_X - NB_Z - NB_P) * 256 + t;   // float4 index 0..16383
        const float* s = (i < 4096) ? W1l : (i < 8192) ? W1r
                        : (i < 12288) ? W2l : W2r;
        float4 v = ((const float4*)s)[i & 4095];
        __half2 h0 = __floats2half2_rn(v.x, v.y);
        __half2 h1 = __floats2half2_rn(v.z, v.w);
        uint2 u;
        u.x = *(uint32_t*)&h0;
        u.y = *(uint32_t*)&h1;
        ((uint2*)g_w16)[i] = u;
    }
}

// ---------------- ELL fill: one pass, no hist/scan ---------------------------
__device__ __forceinline__ int load_idx(const void* ei, long long pos) {
    if (g_not64) return ((const int*)ei)[pos];
    return (int)((const long long*)ei)[pos];
}

__global__ void k_fill(const void* __restrict__ ei, int E) {
    int i = (blockIdx.x * blockDim.x + threadIdx.x) * 2;
#pragma unroll
    for (int q = 0; q < 2; q++) {
        int e = i + q;
        if (e < E) {
            int d = load_idx(ei, (long long)E + e);
            int s = load_idx(ei, e);
            if ((unsigned)d < N_NODES && (unsigned)s < N_NODES) {
                int pos = atomicAdd(&g_cursor[d], 1);
                if (pos < CAP) g_ell[(size_t)d * CAP + pos] = s;
            }
        }
    }
}

// ---------------- aggregation: warp/node, half-warp x 4 edges in flight ------
template <int LAYER>
__global__ void k_agg(void) {
    int gw = (blockIdx.x * blockDim.x + threadIdx.x) >> 5;
    int lane = threadIdx.x & 31;
    if (gw >= N_NODES) return;
    int n = g_cursor[gw];
    int m = n < CAP ? n : CAP;
    const int* col = g_ell + (size_t)gw * CAP;
    int half = lane >> 4;
    int sub = lane & 15;
    const uint4* src = (LAYER == 0) ? (const uint4*)g_x16 : (const uint4*)g_h16;
    float a[8];
#pragma unroll
    for (int q = 0; q < 8; q++) a[q] = 0.f;

    int j = half;
    for (; j + 6 < m; j += 8) {
        int n0 = col[j], n1 = col[j + 2], n2 = col[j + 4], n3 = col[j + 6];
        uint4 u0 = src[(size_t)n0 * 16 + sub];
        uint4 u1 = src[(size_t)n1 * 16 + sub];
        uint4 u2 = src[(size_t)n2 * 16 + sub];
        uint4 u3 = src[(size_t)n3 * 16 + sub];
        float2 f;
        f = __half22float2(*(__half2*)&u0.x); a[0] += f.x; a[1] += f.y;
        f = __half22float2(*(__half2*)&u0.y); a[2] += f.x; a[3] += f.y;
        f = __half22float2(*(__half2*)&u0.z); a[4] += f.x; a[5] += f.y;
        f = __half22float2(*(__half2*)&u0.w); a[6] += f.x; a[7] += f.y;
        f = __half22float2(*(__half2*)&u1.x); a[0] += f.x; a[1] += f.y;
        f = __half22float2(*(__half2*)&u1.y); a[2] += f.x; a[3] += f.y;
        f = __half22float2(*(__half2*)&u1.z); a[4] += f.x; a[5] += f.y;
        f = __half22float2(*(__half2*)&u1.w); a[6] += f.x; a[7] += f.y;
        f = __half22float2(*(__half2*)&u2.x); a[0] += f.x; a[1] += f.y;
        f = __half22float2(*(__half2*)&u2.y); a[2] += f.x; a[3] += f.y;
        f = __half22float2(*(__half2*)&u2.z); a[4] += f.x; a[5] += f.y;
        f = __half22float2(*(__half2*)&u2.w); a[6] += f.x; a[7] += f.y;
        f = __half22float2(*(__half2*)&u3.x); a[0] += f.x; a[1] += f.y;
        f = __half22float2(*(__half2*)&u3.y); a[2] += f.x; a[3] += f.y;
        f = __half22float2(*(__half2*)&u3.z); a[4] += f.x; a[5] += f.y;
        f = __half22float2(*(__half2*)&u3.w); a[6] += f.x; a[7] += f.y;
    }
    for (; j < m; j += 2) {
        int n0 = col[j];
        uint4 u0 = src[(size_t)n0 * 16 + sub];
        float2 f;
        f = __half22float2(*(__half2*)&u0.x); a[0] += f.x; a[1] += f.y;
        f = __half22float2(*(__half2*)&u0.y); a[2] += f.x; a[3] += f.y;
        f = __half22float2(*(__half2*)&u0.z); a[4] += f.x; a[5] += f.y;
        f = __half22float2(*(__half2*)&u0.w); a[6] += f.x; a[7] += f.y;
    }
#pragma unroll
    for (int q = 0; q < 8; q++)
        a[q] += __shfl_down_sync(0xffffffffu, a[q], 16);
    if (half == 0) {
        float inv = 1.0f / fmaxf((float)n, 1.0f);
        __half2 h0 = __floats2half2_rn(a[0] * inv, a[1] * inv);
        __half2 h1 = __floats2half2_rn(a[2] * inv, a[3] * inv);
        __half2 h2 = __floats2half2_rn(a[4] * inv, a[5] * inv);
        __half2 h3 = __floats2half2_rn(a[6] * inv, a[7] * inv);
        uint4 o;
        o.x = *(uint32_t*)&h0;
        o.y = *(uint32_t*)&h1;
        o.z = *(uint32_t*)&h2;
        o.w = *(uint32_t*)&h3;
        ((uint4*)g_agg16)[(size_t)gw * 16 + sub] = o;
    }
}

// ---------------- fp16 mma helper ---------------------------------------------
__device__ __forceinline__ void mma_f16(float d[4], uint32_t a0, uint32_t a1,
                                        uint32_t a2, uint32_t a3,
                                        uint32_t b0, uint32_t b1) {
    asm volatile(
        "mma.sync.aligned.m16n8k16.row.col.f32.f16.f16.f32 "
        "{%0,%1,%2,%3}, {%4,%5,%6,%7}, {%8,%9}, {%0,%1,%2,%3};\n"
        : "+f"(d[0]), "+f"(d[1]), "+f"(d[2]), "+f"(d[3])
        : "r"(a0), "r"(a1), "r"(a2), "r"(a3), "r"(b0), "r"(b1));
}

// ---------------- fused fp16 GEMM: persistent tiles, 3-stage cp.async --------
// grid 296 persistent blocks loop over 782 row tiles of 128.
// block 256 thr; warp tile 32x64; K=256 in 8 chunks of 32; XOR-swizzled smem.
// LAYER 0: A=[agg16|x16], out -> g_h16 (relu). LAYER 1: A=[agg16|h16], out fp32.
template <int LAYER>
__global__ void __launch_bounds__(256)
k_gemm_mma(const float* __restrict__ bb, float* __restrict__ OUT) {
    __shared__ __align__(16) __half As16[3][BM][32];   // 24 KB
    __shared__ __align__(16) __half Ws16[3][32][128];  // 24 KB

    int tid  = threadIdx.x;
    int warp = tid >> 5;
    int lane = tid & 31;
    int rg = warp >> 1;
    int cg = warp & 1;
    int gid = lane >> 2;
    int tig = lane & 3;
    int quad = lane >> 3;
    int lr   = lane & 7;

    const __half* Wbase = g_w16 + LAYER * 32768;

    // bias regs are tile-invariant
    float bv[8][2];
#pragma unroll
    for (int n = 0; n < 8; n++) {
        bv[n][0] = bb[cg * 64 + n * 8 + tig * 2];
        bv[n][1] = bb[cg * 64 + n * 8 + tig * 2 + 1];
    }

    for (int tile = blockIdx.x; tile < NTILES; tile += GEMM_GRID) {
        int row0 = tile * BM;

        auto issue_chunk = [&](int ch) {
            const __half* Wsrc = Wbase + (ch < 4 ? 0 : 16384);
            const __half* Asrc = (ch < 4) ? g_agg16
                                          : (LAYER == 0 ? g_x16 : g_h16);
            int kcol = (ch & 3) * 32;
            int buf = ch % 3;
#pragma unroll
            for (int j = 0; j < 2; j++) {
                int u = tid + j * 256;
                int kk = u >> 4, c16 = u & 15;            // W: 16 chunks/row
                int wc = (c16 ^ (kk & 7)) * 8;
                uint32_t wdst =
                    (uint32_t)__cvta_generic_to_shared(&Ws16[buf][kk][wc]);
                const void* wsrc = Wsrc + (size_t)(kcol + kk) * 128 + c16 * 8;
                asm volatile("cp.async.cg.shared.global [%0], [%1], 16;"
                             :: "r"(wdst), "l"(wsrc));
                int r = u >> 2, ac = u & 3;               // A: 4 chunks/row
                int grow = row0 + r;
                int asw = (ac ^ ((r >> 1) & 3)) * 8;
                uint32_t adst =
                    (uint32_t)__cvta_generic_to_shared(&As16[buf][r][asw]);
                const void* asrc = Asrc +
                    (size_t)(grow < N_NODES ? grow : 0) * 128 + kcol + ac * 8;
                int sz = (grow < N_NODES) ? 16 : 0;       // OOB rows zero-fill
                asm volatile("cp.async.cg.shared.global [%0], [%1], 16, %2;"
                             :: "r"(adst), "l"(asrc), "r"(sz));
            }
            asm volatile("cp.async.commit_group;");
        };

        float acc[2][8][4];
#pragma unroll
        for (int m = 0; m < 2; m++)
#pragma unroll
            for (int n = 0; n < 8; n++)
#pragma unroll
                for (int j = 0; j < 4; j++) acc[m][n][j] = 0.f;

        issue_chunk(0);
        issue_chunk(1);

        for (int ch = 0; ch < 8; ch++) {
            if (ch < 6) { asm volatile("cp.async.wait_group 1;"); }
            else        { asm volatile("cp.async.wait_group 0;"); }
            __syncthreads();                   // chunk ch resident
            if (ch < 6) issue_chunk(ch + 2);
            int buf = ch % 3;

#pragma unroll
            for (int ks = 0; ks < 2; ks++) {
                uint32_t a[2][4];
#pragma unroll
                for (int m = 0; m < 2; m++) {
                    int row = rg * 32 + m * 16 + (quad & 1) * 8 + lr;
                    int cchunk = ks * 2 + (quad >> 1);
                    int col = (cchunk ^ ((row >> 1) & 3)) * 8;
                    uint32_t saddr =
                        (uint32_t)__cvta_generic_to_shared(&As16[buf][row][col]);
                    asm volatile(
                        "ldmatrix.sync.aligned.m8n8.x4.shared.b16 "
                        "{%0,%1,%2,%3}, [%4];"
                        : "=r"(a[m][0]), "=r"(a[m][1]), "=r"(a[m][2]),
                          "=r"(a[m][3])
                        : "r"(saddr));
                }
#pragma unroll
                for (int np = 0; np < 4; np++) {
                    int krow = ks * 16 + (lane & 15);
                    int cc = cg * 8 + np * 2 + (lane >> 4);
                    int ccol = (cc ^ (krow & 7)) * 8;
                    uint32_t saddr =
                        (uint32_t)__cvta_generic_to_shared(&Ws16[buf][krow][ccol]);
                    uint32_t b0, b1, b2, b3;
                    asm volatile(
                        "ldmatrix.sync.aligned.m8n8.x4.trans.shared.b16 "
                        "{%0,%1,%2,%3}, [%4];"
                        : "=r"(b0), "=r"(b1), "=r"(b2), "=r"(b3) : "r"(saddr));
                    mma_f16(acc[0][2 * np],     a[0][0], a[0][1], a[0][2], a[0][3], b0, b1);
                    mma_f16(acc[1][2 * np],     a[1][0], a[1][1], a[1][2], a[1][3], b0, b1);
                    mma_f16(acc[0][2 * np + 1], a[0][0], a[0][1], a[0][2], a[0][3], b2, b3);
                    mma_f16(acc[1][2 * np + 1], a[1][0], a[1][1], a[1][2], a[1][3], b2, b3);
                }
            }
        }
        __syncthreads();

        // RowS scratch aliases the (now dead) As16 buffer
        float* RowS = (float*)&As16[0][0][0];   // [2][BM]

        // ---- epilogue: bias, row sumsq, cross-colgroup reduce, normalize ----
#pragma unroll
        for (int m = 0; m < 2; m++) {
            float s0 = 0.f, s1 = 0.f;
#pragma unroll
            for (int n = 0; n < 8; n++) {
                acc[m][n][0] += bv[n][0];
                acc[m][n][1] += bv[n][1];
                acc[m][n][2] += bv[n][0];
                acc[m][n][3] += bv[n][1];
                s0 = fmaf(acc[m][n][0], acc[m][n][0], s0);
                s0 = fmaf(acc[m][n][1], acc[m][n][1], s0);
                s1 = fmaf(acc[m][n][2], acc[m][n][2], s1);
                s1 = fmaf(acc[m][n][3], acc[m][n][3], s1);
            }
            s0 += __shfl_xor_sync(0xffffffffu, s0, 1);
            s0 += __shfl_xor_sync(0xffffffffu, s0, 2);
            s1 += __shfl_xor_sync(0xffffffffu, s1, 1);
            s1 += __shfl_xor_sync(0xffffffffu, s1, 2);
            if (tig == 0) {
                RowS[cg * BM + rg * 32 + m * 16 + gid]     = s0;
                RowS[cg * BM + rg * 32 + m * 16 + gid + 8] = s1;
            }
        }
        __syncthreads();

#pragma unroll
        for (int m = 0; m < 2; m++) {
            int rl = rg * 32 + m * 16 + gid;
            int rh = rl + 8;
            float inv0 = 1.0f / fmaxf(sqrtf(RowS[rl] + RowS[BM + rl]), 1e-12f);
            float inv1 = 1.0f / fmaxf(sqrtf(RowS[rh] + RowS[BM + rh]), 1e-12f);
            int glo = row0 + rl, ghi = row0 + rh;
#pragma unroll
            for (int p = 0; p < 2; p++) {
                int grow = p ? ghi : glo;
                float inv = p ? inv1 : inv0;
                int o0i = p ? 2 : 0;
                if (grow >= N_NODES) continue;
                if (LAYER == 0) {
                    __half* hp = g_h16 + (size_t)grow * 128 + cg * 64 + tig * 2;
#pragma unroll
                    for (int n = 0; n < 8; n++) {
                        float o0 = fmaxf(acc[m][n][o0i] * inv, 0.f);
                        float o1 = fmaxf(acc[m][n][o0i + 1] * inv, 0.f);
                        *(__half2*)(hp + n * 8) = __floats2half2_rn(o0, o1);
                    }
                } else {
                    float* dp = OUT + (size_t)grow * 128 + cg * 64 + tig * 2;
#pragma unroll
                    for (int n = 0; n < 8; n++) {
                        float o0 = acc[m][n][o0i] * inv;
                        float o1 = acc[m][n][o0i + 1] * inv;
                        *(float2*)(dp + n * 8) = make_float2(o0, o1);
                    }
                }
            }
        }
        __syncthreads();   // RowS reads done before next tile's chunk 0 cp.async
    }
}

// ---------------- launch ------------------------------------------------------
extern "C" void kernel_launch(void* const* d_in, const int* in_sizes, int n_in,
                              void* d_out, int out_size) {
    const float* x   = (const float*)d_in[0];
    const void*  ei  = d_in[1];
    const float* W1l = (const float*)d_in[2];
    const float* b1  = (const float*)d_in[3];
    const float* W1r = (const float*)d_in[4];
    const float* W2l = (const float*)d_in[5];
    const float* b2  = (const float*)d_in[6];
    const float* W2r = (const float*)d_in[7];

    int E = in_sizes[1] / 2;
    float* out = (float*)d_out;

    int eb2 = (E / 2 + 255) / 256;

    k_prep<<<NB_X + NB_Z + NB_P + NB_W, 256>>>(x, ei, W1l, W1r, W2l, W2r, E);
    k_fill<<<eb2, 256>>>(ei, E);

    int aggBlocks = (N_NODES * 32 + 255) / 256;

    // layer 1: agg(x16) -> gemm -> g_h16 (normalize + relu)
    k_agg<0><<<aggBlocks, 256>>>();
    k_gemm_mma<0><<<GEMM_GRID, 256>>>(b1, out);

    // layer 2: agg(g_h16) -> gemm -> out (normalize)
    k_agg<1><<<aggBlocks, 256>>>();
    k_gemm_mma<1><<<GEMM_GRID, 256>>>(b2, out);
}

// round 16
// speedup vs baseline: 1.1321x; 1.0324x over previous
#include <cuda_runtime.h>
#include <cuda_fp16.h>
#include <stdint.h>

#define N_NODES 100000
#define D 128
#define MAX_E 1600000
#define BM 128
#define CAP 96            // ELL capacity per node; Poisson(16) => P(deg>96) ~ 0

// ---------------- scratch (static device globals; no runtime alloc) ----------
__device__ __align__(16) int    g_cursor[N_NODES];          // per-node edge count
__device__ __align__(16) int    g_ell[(size_t)N_NODES * CAP];
__device__ __align__(16) __half g_agg16[(size_t)N_NODES * D];
__device__ __align__(16) __half g_x16[(size_t)N_NODES * D];
__device__ __align__(16) __half g_h16[(size_t)N_NODES * D];
__device__ __align__(16) __half g_w16[4 * 128 * 128];   // [W1l|W1r|W2l|W2r] fp16
__device__ int g_not64 = 0;   // sticky dtype flag (set-once, stable across replays)

// ---------------- fused prologue: tohalf | zero_cursor | probe | W->fp16 -----
#define NB_X 12500          // N_NODES*D/4 float4s / 256
#define NB_Z 391
#define NB_P 16
#define NB_W 64             // 4*128*128 floats / 4 / 256

__global__ void k_prep(const float* __restrict__ x, const void* __restrict__ ei,
                       const float* __restrict__ W1l, const float* __restrict__ W1r,
                       const float* __restrict__ W2l, const float* __restrict__ W2r,
                       int E) {
    int b = blockIdx.x;
    int t = threadIdx.x;
    if (b < NB_X) {                              // x -> fp16
        int i = b * 256 + t;
        float4 v = ((const float4*)x)[i];
        __half2 h0 = __floats2half2_rn(v.x, v.y);
        __half2 h1 = __floats2half2_rn(v.z, v.w);
        uint2 u;
        u.x = *(uint32_t*)&h0;
        u.y = *(uint32_t*)&h1;
        ((uint2*)g_x16)[i] = u;
    } else if (b < NB_X + NB_Z) {                // zero per-node cursors
        int i = (b - NB_X) * 256 + t;
        if (i < N_NODES) g_cursor[i] = 0;
    } else if (b < NB_X + NB_Z + NB_P) {         // dtype probe (sticky)
        int i = (b - NB_X - NB_Z) * 256 + t;
        int n = E < 4096 ? E : 4096;
        if (i < n) {
            long long v = ((const long long*)ei)[i];
            if (v < 0 || v >= N_NODES) g_not64 = 1;   // benign same-value race
        }
    } else {                                     // W -> fp16
        int i = (b - NB_X - NB_Z - NB_P) * 256 + t;   // float4 index 0..16383
        const float* s = (i < 4096) ? W1l : (i < 8192) ? W1r
                        : (i < 12288) ? W2l : W2r;
        float4 v = ((const float4*)s)[i & 4095];
        __half2 h0 = __floats2half2_rn(v.x, v.y);
        __half2 h1 = __floats2half2_rn(v.z, v.w);
        uint2 u;
        u.x = *(uint32_t*)&h0;
        u.y = *(uint32_t*)&h1;
        ((uint2*)g_w16)[i] = u;
    }
}

// ---------------- ELL fill: one pass, vectorized index loads -----------------
__global__ void k_fill(const void* __restrict__ ei, int E) {
    int i = (blockIdx.x * blockDim.x + threadIdx.x) * 2;
    if (i >= E) return;
    int d0, s0, d1 = -1, s1 = -1;
    bool two = (i + 1 < E);
    if (g_not64) {                               // int32: paired 8B loads
        const int* p = (const int*)ei;
        if (two) {
            int2 dv = *(const int2*)(p + (size_t)E + i);
            int2 sv = *(const int2*)(p + i);
            d0 = dv.x; d1 = dv.y; s0 = sv.x; s1 = sv.y;
        } else {
            d0 = p[(size_t)E + i]; s0 = p[i];
        }
    } else {                                     // int64 path
        const long long* p = (const long long*)ei;
        d0 = (int)p[(size_t)E + i]; s0 = (int)p[i];
        if (two) { d1 = (int)p[(size_t)E + i + 1]; s1 = (int)p[i + 1]; }
    }
    if ((unsigned)d0 < N_NODES && (unsigned)s0 < N_NODES) {
        int pos = atomicAdd(&g_cursor[d0], 1);
        if (pos < CAP) g_ell[(size_t)d0 * CAP + pos] = s0;
    }
    if (two && (unsigned)d1 < N_NODES && (unsigned)s1 < N_NODES) {
        int pos = atomicAdd(&g_cursor[d1], 1);
        if (pos < CAP) g_ell[(size_t)d1 * CAP + pos] = s1;
    }
}

// ---------------- aggregation: warp/node, half-warp x 4 edges in flight ------
template <int LAYER>
__global__ void k_agg(void) {
    int gw = (blockIdx.x * blockDim.x + threadIdx.x) >> 5;
    int lane = threadIdx.x & 31;
    if (gw >= N_NODES) return;
    int n = g_cursor[gw];
    int m = n < CAP ? n : CAP;
    const int* col = g_ell + (size_t)gw * CAP;
    int half = lane >> 4;
    int sub = lane & 15;
    const uint4* src = (LAYER == 0) ? (const uint4*)g_x16 : (const uint4*)g_h16;
    float a[8];
#pragma unroll
    for (int q = 0; q < 8; q++) a[q] = 0.f;

    int j = half;
    for (; j + 6 < m; j += 8) {
        int n0 = col[j], n1 = col[j + 2], n2 = col[j + 4], n3 = col[j + 6];
        uint4 u0 = src[(size_t)n0 * 16 + sub];
        uint4 u1 = src[(size_t)n1 * 16 + sub];
        uint4 u2 = src[(size_t)n2 * 16 + sub];
        uint4 u3 = src[(size_t)n3 * 16 + sub];
        float2 f;
        f = __half22float2(*(__half2*)&u0.x); a[0] += f.x; a[1] += f.y;
        f = __half22float2(*(__half2*)&u0.y); a[2] += f.x; a[3] += f.y;
        f = __half22float2(*(__half2*)&u0.z); a[4] += f.x; a[5] += f.y;
        f = __half22float2(*(__half2*)&u0.w); a[6] += f.x; a[7] += f.y;
        f = __half22float2(*(__half2*)&u1.x); a[0] += f.x; a[1] += f.y;
        f = __half22float2(*(__half2*)&u1.y); a[2] += f.x; a[3] += f.y;
        f = __half22float2(*(__half2*)&u1.z); a[4] += f.x; a[5] += f.y;
        f = __half22float2(*(__half2*)&u1.w); a[6] += f.x; a[7] += f.y;
        f = __half22float2(*(__half2*)&u2.x); a[0] += f.x; a[1] += f.y;
        f = __half22float2(*(__half2*)&u2.y); a[2] += f.x; a[3] += f.y;
        f = __half22float2(*(__half2*)&u2.z); a[4] += f.x; a[5] += f.y;
        f = __half22float2(*(__half2*)&u2.w); a[6] += f.x; a[7] += f.y;
        f = __half22float2(*(__half2*)&u3.x); a[0] += f.x; a[1] += f.y;
        f = __half22float2(*(__half2*)&u3.y); a[2] += f.x; a[3] += f.y;
        f = __half22float2(*(__half2*)&u3.z); a[4] += f.x; a[5] += f.y;
        f = __half22float2(*(__half2*)&u3.w); a[6] += f.x; a[7] += f.y;
    }
    for (; j < m; j += 2) {
        int n0 = col[j];
        uint4 u0 = src[(size_t)n0 * 16 + sub];
        float2 f;
        f = __half22float2(*(__half2*)&u0.x); a[0] += f.x; a[1] += f.y;
        f = __half22float2(*(__half2*)&u0.y); a[2] += f.x; a[3] += f.y;
        f = __half22float2(*(__half2*)&u0.z); a[4] += f.x; a[5] += f.y;
        f = __half22float2(*(__half2*)&u0.w); a[6] += f.x; a[7] += f.y;
    }
#pragma unroll
    for (int q = 0; q < 8; q++)
        a[q] += __shfl_down_sync(0xffffffffu, a[q], 16);
    if (half == 0) {
        float inv = 1.0f / fmaxf((float)n, 1.0f);
        __half2 h0 = __floats2half2_rn(a[0] * inv, a[1] * inv);
        __half2 h1 = __floats2half2_rn(a[2] * inv, a[3] * inv);
        __half2 h2 = __floats2half2_rn(a[4] * inv, a[5] * inv);
        __half2 h3 = __floats2half2_rn(a[6] * inv, a[7] * inv);
        uint4 o;
        o.x = *(uint32_t*)&h0;
        o.y = *(uint32_t*)&h1;
        o.z = *(uint32_t*)&h2;
        o.w = *(uint32_t*)&h3;
        ((uint4*)g_agg16)[(size_t)gw * 16 + sub] = o;
    }
}

// ---------------- fp16 mma helper ---------------------------------------------
__device__ __forceinline__ void mma_f16(float d[4], uint32_t a0, uint32_t a1,
                                        uint32_t a2, uint32_t a3,
                                        uint32_t b0, uint32_t b1) {
    asm volatile(
        "mma.sync.aligned.m16n8k16.row.col.f32.f16.f16.f32 "
        "{%0,%1,%2,%3}, {%4,%5,%6,%7}, {%8,%9}, {%0,%1,%2,%3};\n"
        : "+f"(d[0]), "+f"(d[1]), "+f"(d[2]), "+f"(d[3])
        : "r"(a0), "r"(a1), "r"(a2), "r"(a3), "r"(b0), "r"(b1));
}

// ---------------- fused fp16 GEMM: 3-stage cp.async pipeline, XOR swizzle ----
// block 256 thr; tile 128x128; warp tile 32x64; K=256 in 8 chunks of 32.
// A stage [128][32] halves, chunk swizzle c ^= (r>>1)&3.
// W stage [32][128] halves, chunk swizzle c ^= k&7.
// LAYER 0: A=[agg16|x16], out -> g_h16 (relu). LAYER 1: A=[agg16|h16], out fp32.
template <int LAYER>
__global__ void __launch_bounds__(256)
k_gemm_mma(const float* __restrict__ bb, float* __restrict__ OUT) {
    __shared__ __align__(16) __half As16[3][BM][32];   // 24 KB
    __shared__ __align__(16) __half Ws16[3][32][128];  // 24 KB

    int tid  = threadIdx.x;
    int warp = tid >> 5;
    int lane = tid & 31;
    int rg = warp >> 1;
    int cg = warp & 1;
    int gid = lane >> 2;
    int tig = lane & 3;
    int quad = lane >> 3;
    int lr   = lane & 7;
    int row0 = blockIdx.x * BM;

    const __half* Wbase = g_w16 + LAYER * 32768;

    // cp.async chunk issue: 2x 16B for W + 2x 16B for A per thread (swizzled)
    auto issue_chunk = [&](int ch) {
        const __half* Wsrc = Wbase + (ch < 4 ? 0 : 16384);
        const __half* Asrc = (ch < 4) ? g_agg16 : (LAYER == 0 ? g_x16 : g_h16);
        int kcol = (ch & 3) * 32;
        int buf = ch % 3;
#pragma unroll
        for (int j = 0; j < 2; j++) {
            int u = tid + j * 256;
            int kk = u >> 4, c16 = u & 15;            // W: 16 chunks/row
            int wc = (c16 ^ (kk & 7)) * 8;
            uint32_t wdst = (uint32_t)__cvta_generic_to_shared(&Ws16[buf][kk][wc]);
            const void* wsrc = Wsrc + (size_t)(kcol + kk) * 128 + c16 * 8;
            asm volatile("cp.async.cg.shared.global [%0], [%1], 16;"
                         :: "r"(wdst), "l"(wsrc));
            int r = u >> 2, ac = u & 3;               // A: 4 chunks/row
            int grow = row0 + r;
            int asw = (ac ^ ((r >> 1) & 3)) * 8;
            uint32_t adst = (uint32_t)__cvta_generic_to_shared(&As16[buf][r][asw]);
            const void* asrc = Asrc +
                (size_t)(grow < N_NODES ? grow : 0) * 128 + kcol + ac * 8;
            int sz = (grow < N_NODES) ? 16 : 0;       // OOB rows zero-fill
            asm volatile("cp.async.cg.shared.global [%0], [%1], 16, %2;"
                         :: "r"(adst), "l"(asrc), "r"(sz));
        }
        asm volatile("cp.async.commit_group;");
    };

    float acc[2][8][4];
#pragma unroll
    for (int m = 0; m < 2; m++)
#pragma unroll
        for (int n = 0; n < 8; n++)
#pragma unroll
            for (int j = 0; j < 4; j++) acc[m][n][j] = 0.f;

    issue_chunk(0);
    issue_chunk(1);

    for (int ch = 0; ch < 8; ch++) {
        if (ch < 6) { asm volatile("cp.async.wait_group 1;"); }
        else        { asm volatile("cp.async.wait_group 0;"); }
        __syncthreads();                   // chunk ch resident; mma ch-1 retired
        if (ch < 6) issue_chunk(ch + 2);   // overlaps the next two mma phases
        int buf = ch % 3;

#pragma unroll
        for (int ks = 0; ks < 2; ks++) {
            uint32_t a[2][4];
#pragma unroll
            for (int m = 0; m < 2; m++) {
                int row = rg * 32 + m * 16 + (quad & 1) * 8 + lr;
                int cchunk = ks * 2 + (quad >> 1);
                int col = (cchunk ^ ((row >> 1) & 3)) * 8;
                uint32_t saddr =
                    (uint32_t)__cvta_generic_to_shared(&As16[buf][row][col]);
                asm volatile(
                    "ldmatrix.sync.aligned.m8n8.x4.shared.b16 "
                    "{%0,%1,%2,%3}, [%4];"
                    : "=r"(a[m][0]), "=r"(a[m][1]), "=r"(a[m][2]), "=r"(a[m][3])
                    : "r"(saddr));
            }
#pragma unroll
            for (int np = 0; np < 4; np++) {
                int krow = ks * 16 + (lane & 15);
                int cc = cg * 8 + np * 2 + (lane >> 4);
                int ccol = (cc ^ (krow & 7)) * 8;
                uint32_t saddr =
                    (uint32_t)__cvta_generic_to_shared(&Ws16[buf][krow][ccol]);
                uint32_t b0, b1, b2, b3;
                asm volatile(
                    "ldmatrix.sync.aligned.m8n8.x4.trans.shared.b16 "
                    "{%0,%1,%2,%3}, [%4];"
                    : "=r"(b0), "=r"(b1), "=r"(b2), "=r"(b3) : "r"(saddr));
                mma_f16(acc[0][2 * np],     a[0][0], a[0][1], a[0][2], a[0][3], b0, b1);
                mma_f16(acc[1][2 * np],     a[1][0], a[1][1], a[1][2], a[1][3], b0, b1);
                mma_f16(acc[0][2 * np + 1], a[0][0], a[0][1], a[0][2], a[0][3], b2, b3);
                mma_f16(acc[1][2 * np + 1], a[1][0], a[1][1], a[1][2], a[1][3], b2, b3);
            }
        }
    }
    __syncthreads();

    // RowS scratch aliases the (now dead) As16 buffer
    float* RowS = (float*)&As16[0][0][0];   // [2][BM]

    // ---- epilogue: bias, row sumsq, cross-colgroup reduce, normalize --------
    float bv[8][2];
#pragma unroll
    for (int n = 0; n < 8; n++) {
        bv[n][0] = bb[cg * 64 + n * 8 + tig * 2];
        bv[n][1] = bb[cg * 64 + n * 8 + tig * 2 + 1];
    }

#pragma unroll
    for (int m = 0; m < 2; m++) {
        float s0 = 0.f, s1 = 0.f;
#pragma unroll
        for (int n = 0; n < 8; n++) {
            acc[m][n][0] += bv[n][0];
            acc[m][n][1] += bv[n][1];
            acc[m][n][2] += bv[n][0];
            acc[m][n][3] += bv[n][1];
            s0 = fmaf(acc[m][n][0], acc[m][n][0], s0);
            s0 = fmaf(acc[m][n][1], acc[m][n][1], s0);
            s1 = fmaf(acc[m][n][2], acc[m][n][2], s1);
            s1 = fmaf(acc[m][n][3], acc[m][n][3], s1);
        }
        s0 += __shfl_xor_sync(0xffffffffu, s0, 1);
        s0 += __shfl_xor_sync(0xffffffffu, s0, 2);
        s1 += __shfl_xor_sync(0xffffffffu, s1, 1);
        s1 += __shfl_xor_sync(0xffffffffu, s1, 2);
        if (tig == 0) {
            RowS[cg * BM + rg * 32 + m * 16 + gid]     = s0;
            RowS[cg * BM + rg * 32 + m * 16 + gid + 8] = s1;
        }
    }
    __syncthreads();

#pragma unroll
    for (int m = 0; m < 2; m++) {
        int rl = rg * 32 + m * 16 + gid;
        int rh = rl + 8;
        float inv0 = 1.0f / fmaxf(sqrtf(RowS[rl] + RowS[BM + rl]), 1e-12f);
        float inv1 = 1.0f / fmaxf(sqrtf(RowS[rh] + RowS[BM + rh]), 1e-12f);
        int glo = row0 + rl, ghi = row0 + rh;
#pragma unroll
        for (int p = 0; p < 2; p++) {
            int grow = p ? ghi : glo;
            float inv = p ? inv1 : inv0;
            int o0i = p ? 2 : 0;
            if (grow >= N_NODES) continue;
            if (LAYER == 0) {
                __half* hp = g_h16 + (size_t)grow * 128 + cg * 64 + tig * 2;
#pragma unroll
                for (int n = 0; n < 8; n++) {
                    float o0 = fmaxf(acc[m][n][o0i] * inv, 0.f);
                    float o1 = fmaxf(acc[m][n][o0i + 1] * inv, 0.f);
                    *(__half2*)(hp + n * 8) = __floats2half2_rn(o0, o1);
                }
            } else {
                float* dp = OUT + (size_t)grow * 128 + cg * 64 + tig * 2;
#pragma unroll
                for (int n = 0; n < 8; n++) {
                    float o0 = acc[m][n][o0i] * inv;
                    float o1 = acc[m][n][o0i + 1] * inv;
                    *(float2*)(dp + n * 8) = make_float2(o0, o1);
                }
            }
        }
    }
}

// ---------------- launch ------------------------------------------------------
extern "C" void kernel_launch(void* const* d_in, const int* in_sizes, int n_in,
                              void* d_out, int out_size) {
    const float* x   = (const float*)d_in[0];
    const void*  ei  = d_in[1];
    const float* W1l = (const float*)d_in[2];
    const float* b1  = (const float*)d_in[3];
    const float* W1r = (const float*)d_in[4];
    const float* W2l = (const float*)d_in[5];
    const float* b2  = (const float*)d_in[6];
    const float* W2r = (const float*)d_in[7];

    int E = in_sizes[1] / 2;
    float* out = (float*)d_out;

    int eb2 = (E / 2 + 255) / 256;

    k_prep<<<NB_X + NB_Z + NB_P + NB_W, 256>>>(x, ei, W1l, W1r, W2l, W2r, E);
    k_fill<<<eb2, 256>>>(ei, E);

    int aggBlocks  = (N_NODES * 32 + 255) / 256;
    int gemmBlocks = (N_NODES + BM - 1) / BM;

    // layer 1: agg(x16) -> gemm -> g_h16 (normalize + relu)
    k_agg<0><<<aggBlocks, 256>>>();
    k_gemm_mma<0><<<gemmBlocks, 256>>>(b1, out);

    // layer 2: agg(g_h16) -> gemm -> out (normalize)
    k_agg<1><<<aggBlocks, 256>>>();
    k_gemm_mma<1><<<gemmBlocks, 256>>>(b2, out);
}